// round 4
// baseline (speedup 1.0000x reference)
#include <cuda_runtime.h>
#include <math.h>
#include <stdint.h>

#define M 5
#define NACC 20              // c[5] + packed upper Gram S[15]
#define NB1 592              // pass1 grid
#define NB2 1184             // pass2 grid
#define NTHREADS 256

__device__ float  g_W[M * M];
__device__ float  g_qpk[15];         // Q = W^T W packed upper, off-diag doubled
__device__ float  g_mask[M];
__device__ float  g_y[M];
__device__ double g_partials[NB1 * NACC];

// ---- f32x2 packed helpers (sm_103a) ---------------------------------------
__device__ __forceinline__ uint64_t pk2(float a, float b) {
    uint64_t r;
    asm("mov.b64 %0, {%1, %2};" : "=l"(r) : "f"(a), "f"(b));
    return r;
}
__device__ __forceinline__ void upk2(float& a, float& b, uint64_t v) {
    asm("mov.b64 {%0, %1}, %2;" : "=f"(a), "=f"(b) : "l"(v));
}
__device__ __forceinline__ uint64_t fma2(uint64_t a, uint64_t b, uint64_t c) {
    uint64_t d;
    asm("fma.rn.f32x2 %0, %1, %2, %3;" : "=l"(d) : "l"(a), "l"(b), "l"(c));
    return d;
}
__device__ __forceinline__ uint64_t mul2(uint64_t a, uint64_t b) {
    uint64_t d;
    asm("mul.rn.f32x2 %0, %1, %2;" : "=l"(d) : "l"(a), "l"(b));
    return d;
}
__device__ __forceinline__ uint64_t add2(uint64_t a, uint64_t b) {
    uint64_t d;
    asm("add.rn.f32x2 %0, %1, %2;" : "=l"(d) : "l"(a), "l"(b));
    return d;
}
// dv = 1/(sqrt(ss)+1e-8) ≈ r - 1e-8*r^2, r = rsqrt(ss)   (err ~ (1e-8 r)^2)
__device__ __forceinline__ uint64_t dv2_from_ss2(uint64_t ss2) {
    float sa, sb;
    upk2(sa, sb, ss2);
    float ra = rsqrtf(fmaxf(sa, 1e-16f));
    float rb = rsqrtf(fmaxf(sb, 1e-16f));
    float da = fmaf(-1e-8f * ra, ra, ra);
    float db = fmaf(-1e-8f * rb, rb, rb);
    return pk2(da, db);
}

// ---------------------------------------------------------------------------
// Kernel 1: warp-parallel fp32 5x5 Jacobi eigendecomposition
//   lane j (<5) owns row j of A and row j of V
// ---------------------------------------------------------------------------
__global__ void kwng_setup(const float* __restrict__ K) {
    const unsigned FULL = 0xffffffffu;
    int lane = threadIdx.x;
    int j = (lane < M) ? lane : 0;
    float a[M], v[M];
#pragma unroll
    for (int k = 0; k < M; k++) {
        a[k] = K[j * M + k];
        v[k] = (j == k) ? 1.0f : 0.0f;
    }
    for (int sweep = 0; sweep < 12; sweep++) {
        float off = 0.0f;
#pragma unroll
        for (int k = 0; k < M; k++)
            if (k != j) off += a[k] * a[k];
        if (lane >= M) off = 0.0f;
#pragma unroll
        for (int o = 16; o > 0; o >>= 1) off += __shfl_xor_sync(FULL, off, o);
        if (off < 2e-18f) break;
#pragma unroll
        for (int p = 0; p < M; p++) {
#pragma unroll
            for (int q = p + 1; q < M; q++) {
                float apq = __shfl_sync(FULL, a[q], p);
                float app = __shfl_sync(FULL, a[p], p);
                float aqq = __shfl_sync(FULL, a[q], q);
                if (fabsf(apq) < 1e-30f) continue;   // uniform
                float theta = (aqq - app) / (2.0f * apq);
                float t = ((theta >= 0.0f) ? 1.0f : -1.0f) /
                          (fabsf(theta) + sqrtf(theta * theta + 1.0f));
                float c = rsqrtf(t * t + 1.0f);
                float s = t * c;
                // column rotation (lane-local on own row)
                float tp = a[p], tq = a[q];
                a[p] = c * tp - s * tq;
                a[q] = s * tp + c * tq;
                tp = v[p]; tq = v[q];
                v[p] = c * tp - s * tq;
                v[q] = s * tp + c * tq;
                // row rotation (rows p and q)
                float na[M];
#pragma unroll
                for (int k = 0; k < M; k++) {
                    float apk = __shfl_sync(FULL, a[k], p);
                    float aqk = __shfl_sync(FULL, a[k], q);
                    na[k] = (j == p) ? (c * apk - s * aqk)
                          : (j == q) ? (s * apk + c * aqk) : a[k];
                }
#pragma unroll
                for (int k = 0; k < M; k++) a[k] = na[k];
            }
        }
    }
    // eigenvalue of own row = a[j]; eigenvector i has component v[j][i]=v[i] at lane j
    float lam = a[j];
    bool keep = lam > 0.0f;                 // THRESH = 0
    float w = keep ? (1.0f / sqrtf(lam)) : 0.0f;
    float w2 = w * w;                       // = mask/lam
    if (lane < M) g_mask[lane] = keep ? 1.0f : 0.0f;
#pragma unroll
    for (int i = 0; i < M; i++) {
        float wi = __shfl_sync(FULL, w, i);
        if (lane < M) g_W[i * M + lane] = wi * v[i];
    }
    // Q[j][k] = sum_i w_i^2 v[j][i] v[k][i]; lane j computes row j (k >= j)
    float invl[M];
#pragma unroll
    for (int i = 0; i < M; i++) invl[i] = __shfl_sync(FULL, w2, i);
#pragma unroll
    for (int k = 0; k < M; k++) {
        float q = 0.0f;
#pragma unroll
        for (int i = 0; i < M; i++)
            q += invl[i] * v[i] * __shfl_sync(FULL, v[i], k);
        if (lane < M && k >= j) {
            int base = j * M - (j * (j - 1)) / 2;   // packed row offset
            g_qpk[base + (k - j)] = (k == j) ? q : 2.0f * q;
        }
    }
}

// ---------------------------------------------------------------------------
// Kernel 2: streaming reduction pass, f32x2-packed
// ---------------------------------------------------------------------------
__global__ void __launch_bounds__(NTHREADS, 2)
kwng_pass1(const float* __restrict__ T, const float* __restrict__ g, int D) {
    uint64_t qpk2[15];
#pragma unroll
    for (int i = 0; i < 15; i++) {
        float q = g_qpk[i];
        qpk2[i] = pk2(q, q);
    }
    uint64_t acc2[NACC];
    const uint64_t zz = pk2(0.0f, 0.0f);
#pragma unroll
    for (int a = 0; a < NACC; a++) acc2[a] = zz;

    const float4* __restrict__ T4 = (const float4*)T;
    const float4* __restrict__ g4 = (const float4*)g;
    const int n4 = D >> 2;

    for (int idx = blockIdx.x * blockDim.x + threadIdx.x; idx < n4;
         idx += gridDim.x * blockDim.x) {
        float4 tv[M];
#pragma unroll
        for (int j = 0; j < M; j++) tv[j] = T4[(size_t)j * n4 + idx];
        float4 gv = g4[idx];
        const uint64_t* gpp = reinterpret_cast<const uint64_t*>(&gv);
#pragma unroll
        for (int pr = 0; pr < 2; pr++) {
            uint64_t t2[M];
#pragma unroll
            for (int j = 0; j < M; j++)
                t2[j] = reinterpret_cast<const uint64_t*>(&tv[j])[pr];
            uint64_t g2 = gpp[pr];
            uint64_t ss2;
            {
                int qi = 0;
                uint64_t inner = mul2(qpk2[qi++], t2[0]);
#pragma unroll
                for (int k = 1; k < M; k++) inner = fma2(qpk2[qi++], t2[k], inner);
                ss2 = mul2(inner, t2[0]);
#pragma unroll
                for (int j = 1; j < M; j++) {
                    inner = mul2(qpk2[qi++], t2[j]);
#pragma unroll
                    for (int k = j + 1; k < M; k++)
                        inner = fma2(qpk2[qi++], t2[k], inner);
                    ss2 = fma2(inner, t2[j], ss2);
                }
            }
            uint64_t dv2 = dv2_from_ss2(ss2);
            uint64_t dvg2 = mul2(dv2, g2);
#pragma unroll
            for (int j = 0; j < M; j++) acc2[j] = fma2(t2[j], dvg2, acc2[j]);
            int ai = M;
#pragma unroll
            for (int j = 0; j < M; j++) {
                uint64_t u2 = mul2(dv2, t2[j]);
#pragma unroll
                for (int k = j; k < M; k++) {
                    acc2[ai] = fma2(u2, t2[k], acc2[ai]);
                    ai++;
                }
            }
        }
    }

    __shared__ float sred[NTHREADS / 32][NACC];
    int lane = threadIdx.x & 31;
    int warp = threadIdx.x >> 5;
#pragma unroll
    for (int a = 0; a < NACC; a++) {
        float lo, hi;
        upk2(lo, hi, acc2[a]);
        float v = lo + hi;
#pragma unroll
        for (int off = 16; off > 0; off >>= 1)
            v += __shfl_down_sync(0xffffffffu, v, off);
        if (lane == 0) sred[warp][a] = v;
    }
    __syncthreads();
    if (threadIdx.x < NACC) {
        double s = 0.0;
#pragma unroll
        for (int w = 0; w < NTHREADS / 32; w++) s += (double)sred[w][threadIdx.x];
        g_partials[(size_t)blockIdx.x * NACC + threadIdx.x] = s;
    }
}

// ---------------------------------------------------------------------------
// Kernel 3: reduce partials + fp32 tiny solve
//   G = W S W^T + eps*diag(mask);  z = G^{-1}(W c);  y = W^T z
// ---------------------------------------------------------------------------
__global__ void kwng_reduce_solve() {
    __shared__ float sacc[NACC];
    int a = threadIdx.x >> 5;
    int lane = threadIdx.x & 31;
    if (a < NACC) {
        double s = 0.0;
        for (int b = lane; b < NB1; b += 32)
            s += g_partials[(size_t)b * NACC + a];
#pragma unroll
        for (int off = 16; off > 0; off >>= 1)
            s += __shfl_down_sync(0xffffffffu, s, off);
        if (lane == 0) sacc[a] = (float)s;
    }
    __syncthreads();
    if (threadIdx.x == 0) {
        float c[M], S[M][M], W[M][M];
#pragma unroll
        for (int i = 0; i < M; i++) c[i] = sacc[i];
        int ai = M;
#pragma unroll
        for (int j = 0; j < M; j++)
#pragma unroll
            for (int k = j; k < M; k++) {
                S[j][k] = sacc[ai];
                S[k][j] = sacc[ai];
                ai++;
            }
#pragma unroll
        for (int i = 0; i < M; i++)
#pragma unroll
            for (int j = 0; j < M; j++) W[i][j] = g_W[i * M + j];

        float WS[M][M], G[M][M], rhs[M];
#pragma unroll
        for (int i = 0; i < M; i++)
#pragma unroll
            for (int k = 0; k < M; k++) {
                float s = 0.0f;
#pragma unroll
                for (int j = 0; j < M; j++) s = fmaf(W[i][j], S[j][k], s);
                WS[i][k] = s;
            }
#pragma unroll
        for (int i = 0; i < M; i++)
#pragma unroll
            for (int l = 0; l < M; l++) {
                float s = 0.0f;
#pragma unroll
                for (int k = 0; k < M; k++) s = fmaf(WS[i][k], W[l][k], s);
                G[i][l] = s;
            }
#pragma unroll
        for (int i = 0; i < M; i++) G[i][i] += 1e-5f * g_mask[i];
#pragma unroll
        for (int i = 0; i < M; i++) {
            float s = 0.0f;
#pragma unroll
            for (int j = 0; j < M; j++) s = fmaf(W[i][j], c[j], s);
            rhs[i] = s;
        }
        // fp32 Gaussian elimination with partial pivoting
        for (int col = 0; col < M; col++) {
            int piv = col;
            for (int r = col + 1; r < M; r++)
                if (fabsf(G[r][col]) > fabsf(G[piv][col])) piv = r;
            if (piv != col) {
                for (int cc = 0; cc < M; cc++) {
                    float tmp = G[col][cc]; G[col][cc] = G[piv][cc]; G[piv][cc] = tmp;
                }
                float tb = rhs[col]; rhs[col] = rhs[piv]; rhs[piv] = tb;
            }
            float inv = 1.0f / G[col][col];
            for (int r = col + 1; r < M; r++) {
                float f = G[r][col] * inv;
                for (int cc = col; cc < M; cc++) G[r][cc] -= f * G[col][cc];
                rhs[r] -= f * rhs[col];
            }
        }
        float z[M];
        for (int r = M - 1; r >= 0; r--) {
            float s = rhs[r];
            for (int cc = r + 1; cc < M; cc++) s -= G[r][cc] * z[cc];
            z[r] = s / G[r][r];
        }
#pragma unroll
        for (int j = 0; j < M; j++) {
            float s = 0.0f;
#pragma unroll
            for (int i = 0; i < M; i++) s = fmaf(W[i][j], z[i], s);
            g_y[j] = s;
        }
    }
}

// ---------------------------------------------------------------------------
// Kernel 4: map pass, f32x2-packed
// ---------------------------------------------------------------------------
__global__ void __launch_bounds__(NTHREADS, 4)
kwng_pass2(const float* __restrict__ T, const float* __restrict__ g,
           float* __restrict__ out, int D) {
    uint64_t qpk2[15], y2[M];
#pragma unroll
    for (int i = 0; i < 15; i++) {
        float q = g_qpk[i];
        qpk2[i] = pk2(q, q);
    }
#pragma unroll
    for (int i = 0; i < M; i++) {
        float yv = g_y[i];
        y2[i] = pk2(yv, yv);
    }
    const uint64_t eps2 = pk2(1e5f, 1e5f);   // 1/eps

    const float4* __restrict__ T4 = (const float4*)T;
    const float4* __restrict__ g4 = (const float4*)g;
    float4* __restrict__ o4 = (float4*)out;
    const int n4 = D >> 2;

    for (int i = blockIdx.x * blockDim.x + threadIdx.x; i < n4;
         i += gridDim.x * blockDim.x) {
        int idx = n4 - 1 - i;
        float4 tv[M];
#pragma unroll
        for (int j = 0; j < M; j++) tv[j] = T4[(size_t)j * n4 + idx];
        float4 gv = g4[idx];
        const uint64_t* gpp = reinterpret_cast<const uint64_t*>(&gv);
        float4 ov;
        uint64_t* opp = reinterpret_cast<uint64_t*>(&ov);
#pragma unroll
        for (int pr = 0; pr < 2; pr++) {
            uint64_t t2[M];
#pragma unroll
            for (int j = 0; j < M; j++)
                t2[j] = reinterpret_cast<const uint64_t*>(&tv[j])[pr];
            uint64_t ss2;
            {
                int qi = 0;
                uint64_t inner = mul2(qpk2[qi++], t2[0]);
#pragma unroll
                for (int k = 1; k < M; k++) inner = fma2(qpk2[qi++], t2[k], inner);
                ss2 = mul2(inner, t2[0]);
#pragma unroll
                for (int j = 1; j < M; j++) {
                    inner = mul2(qpk2[qi++], t2[j]);
#pragma unroll
                    for (int k = j + 1; k < M; k++)
                        inner = fma2(qpk2[qi++], t2[k], inner);
                    ss2 = fma2(inner, t2[j], ss2);
                }
            }
            uint64_t dv2 = dv2_from_ss2(ss2);
            uint64_t cond2 = mul2(y2[0], t2[0]);
#pragma unroll
            for (int j = 1; j < M; j++) cond2 = fma2(y2[j], t2[j], cond2);
            uint64_t s2 = add2(gpp[pr], cond2);
            s2 = mul2(s2, eps2);
            opp[pr] = mul2(dv2, s2);
        }
        __stcs(&o4[idx], ov);
    }
}

// ---------------------------------------------------------------------------
extern "C" void kernel_launch(void* const* d_in, const int* in_sizes, int n_in,
                              void* d_out, int out_size) {
    const float* K = (const float*)d_in[0];   // [5,5]
    const float* T = (const float*)d_in[1];   // [5, D]
    const float* g = (const float*)d_in[2];   // [D]
    float* out = (float*)d_out;               // [D]
    int D = in_sizes[2];

    kwng_setup<<<1, 32>>>(K);
    kwng_pass1<<<NB1, NTHREADS>>>(T, g, D);
    kwng_reduce_solve<<<1, NACC * 32>>>();
    kwng_pass2<<<NB2, NTHREADS>>>(T, g, out, D);
}

// round 5
// speedup vs baseline: 1.4071x; 1.4071x over previous
#include <cuda_runtime.h>
#include <math.h>
#include <stdint.h>

#define M 5
#define NACC 20              // c[5] + packed upper Gram S[15]
#define NB1 592              // pass1 grid
#define NB2 1184             // pass2 grid
#define NTHREADS 256

__device__ float  g_qpk[15];         // Q = K^-1 packed upper, off-diag doubled
__device__ float  g_y[M];
__device__ double g_partials[NB1 * NACC];

// ---- f32x2 packed helpers (sm_103a) ---------------------------------------
__device__ __forceinline__ uint64_t pk2(float a, float b) {
    uint64_t r;
    asm("mov.b64 %0, {%1, %2};" : "=l"(r) : "f"(a), "f"(b));
    return r;
}
__device__ __forceinline__ void upk2(float& a, float& b, uint64_t v) {
    asm("mov.b64 {%0, %1}, %2;" : "=f"(a), "=f"(b) : "l"(v));
}
__device__ __forceinline__ uint64_t fma2(uint64_t a, uint64_t b, uint64_t c) {
    uint64_t d;
    asm("fma.rn.f32x2 %0, %1, %2, %3;" : "=l"(d) : "l"(a), "l"(b), "l"(c));
    return d;
}
__device__ __forceinline__ uint64_t mul2(uint64_t a, uint64_t b) {
    uint64_t d;
    asm("mul.rn.f32x2 %0, %1, %2;" : "=l"(d) : "l"(a), "l"(b));
    return d;
}
__device__ __forceinline__ uint64_t add2(uint64_t a, uint64_t b) {
    uint64_t d;
    asm("add.rn.f32x2 %0, %1, %2;" : "=l"(d) : "l"(a), "l"(b));
    return d;
}
// dv = 1/(sqrt(ss)+1e-8) ≈ r - 1e-8*r^2, r = rsqrt(ss)
__device__ __forceinline__ uint64_t dv2_from_ss2(uint64_t ss2) {
    float sa, sb;
    upk2(sa, sb, ss2);
    float ra = rsqrtf(fmaxf(sa, 1e-16f));
    float rb = rsqrtf(fmaxf(sb, 1e-16f));
    float da = fmaf(-1e-8f * ra, ra, ra);
    float db = fmaf(-1e-8f * rb, rb, rb);
    return pk2(da, db);
}

// ---------------------------------------------------------------------------
// Kernel 1: Q = K^-1 via fp32 Gauss-Jordan with partial pivoting (1 thread)
//   WtW = V diag(1/s) V^T = K^-1 for full-rank PSD K (mask all ones).
// ---------------------------------------------------------------------------
__global__ void kwng_setup(const float* __restrict__ K) {
    float A[M][M], Q[M][M];
#pragma unroll
    for (int i = 0; i < M; i++)
#pragma unroll
        for (int j = 0; j < M; j++) {
            A[i][j] = K[i * M + j];
            Q[i][j] = (i == j) ? 1.0f : 0.0f;
        }
    for (int col = 0; col < M; col++) {
        int piv = col;
        for (int r = col + 1; r < M; r++)
            if (fabsf(A[r][col]) > fabsf(A[piv][col])) piv = r;
        if (piv != col) {
            for (int c = 0; c < M; c++) {
                float t = A[col][c]; A[col][c] = A[piv][c]; A[piv][c] = t;
                t = Q[col][c]; Q[col][c] = Q[piv][c]; Q[piv][c] = t;
            }
        }
        float inv = 1.0f / A[col][col];
        for (int c = 0; c < M; c++) { A[col][c] *= inv; Q[col][c] *= inv; }
        for (int r = 0; r < M; r++) {
            if (r == col) continue;
            float f = A[r][col];
            for (int c = 0; c < M; c++) {
                A[r][c] = fmaf(-f, A[col][c], A[r][c]);
                Q[r][c] = fmaf(-f, Q[col][c], Q[r][c]);
            }
        }
    }
    // symmetrize (K^-1 is symmetric; average kills GJ asymmetry noise)
    int qi = 0;
#pragma unroll
    for (int j = 0; j < M; j++)
#pragma unroll
        for (int k = j; k < M; k++) {
            float q = 0.5f * (Q[j][k] + Q[k][j]);
            g_qpk[qi++] = (k == j) ? q : 2.0f * q;
        }
}

// ---------------------------------------------------------------------------
// Kernel 2: streaming reduction pass, f32x2-packed
//   ss = t^T Q t ; dv = 1/(sqrt(ss)+1e-8)
//   c_j += dv*g*t_j ; S_jk += dv*t_j*t_k
// ---------------------------------------------------------------------------
__global__ void __launch_bounds__(NTHREADS, 2)
kwng_pass1(const float* __restrict__ T, const float* __restrict__ g, int D) {
    uint64_t qpk2[15];
#pragma unroll
    for (int i = 0; i < 15; i++) {
        float q = g_qpk[i];
        qpk2[i] = pk2(q, q);
    }
    uint64_t acc2[NACC];
    const uint64_t zz = pk2(0.0f, 0.0f);
#pragma unroll
    for (int a = 0; a < NACC; a++) acc2[a] = zz;

    const float4* __restrict__ T4 = (const float4*)T;
    const float4* __restrict__ g4 = (const float4*)g;
    const int n4 = D >> 2;

    for (int idx = blockIdx.x * blockDim.x + threadIdx.x; idx < n4;
         idx += gridDim.x * blockDim.x) {
        float4 tv[M];
#pragma unroll
        for (int j = 0; j < M; j++) tv[j] = T4[(size_t)j * n4 + idx];
        float4 gv = g4[idx];
        const uint64_t* gpp = reinterpret_cast<const uint64_t*>(&gv);
#pragma unroll
        for (int pr = 0; pr < 2; pr++) {
            uint64_t t2[M];
#pragma unroll
            for (int j = 0; j < M; j++)
                t2[j] = reinterpret_cast<const uint64_t*>(&tv[j])[pr];
            uint64_t g2 = gpp[pr];
            uint64_t ss2;
            {
                int qi = 0;
                uint64_t inner = mul2(qpk2[qi++], t2[0]);
#pragma unroll
                for (int k = 1; k < M; k++) inner = fma2(qpk2[qi++], t2[k], inner);
                ss2 = mul2(inner, t2[0]);
#pragma unroll
                for (int j = 1; j < M; j++) {
                    inner = mul2(qpk2[qi++], t2[j]);
#pragma unroll
                    for (int k = j + 1; k < M; k++)
                        inner = fma2(qpk2[qi++], t2[k], inner);
                    ss2 = fma2(inner, t2[j], ss2);
                }
            }
            uint64_t dv2 = dv2_from_ss2(ss2);
            uint64_t dvg2 = mul2(dv2, g2);
#pragma unroll
            for (int j = 0; j < M; j++) acc2[j] = fma2(t2[j], dvg2, acc2[j]);
            int ai = M;
#pragma unroll
            for (int j = 0; j < M; j++) {
                uint64_t u2 = mul2(dv2, t2[j]);
#pragma unroll
                for (int k = j; k < M; k++) {
                    acc2[ai] = fma2(u2, t2[k], acc2[ai]);
                    ai++;
                }
            }
        }
    }

    __shared__ float sred[NTHREADS / 32][NACC];
    int lane = threadIdx.x & 31;
    int warp = threadIdx.x >> 5;
#pragma unroll
    for (int a = 0; a < NACC; a++) {
        float lo, hi;
        upk2(lo, hi, acc2[a]);
        float v = lo + hi;
#pragma unroll
        for (int off = 16; off > 0; off >>= 1)
            v += __shfl_down_sync(0xffffffffu, v, off);
        if (lane == 0) sred[warp][a] = v;
    }
    __syncthreads();
    if (threadIdx.x < NACC) {
        double s = 0.0;
#pragma unroll
        for (int w = 0; w < NTHREADS / 32; w++) s += (double)sred[w][threadIdx.x];
        g_partials[(size_t)blockIdx.x * NACC + threadIdx.x] = s;
    }
}

// ---------------------------------------------------------------------------
// Kernel 3: reduce partials + fp32 tiny solve:  y = (S + eps*K)^-1 c
// ---------------------------------------------------------------------------
__global__ void kwng_reduce_solve(const float* __restrict__ K) {
    __shared__ float sacc[NACC];
    int a = threadIdx.x >> 5;
    int lane = threadIdx.x & 31;
    if (a < NACC) {
        double s = 0.0;
        for (int b = lane; b < NB1; b += 32)
            s += g_partials[(size_t)b * NACC + a];
#pragma unroll
        for (int off = 16; off > 0; off >>= 1)
            s += __shfl_down_sync(0xffffffffu, s, off);
        if (lane == 0) sacc[a] = (float)s;
    }
    __syncthreads();
    if (threadIdx.x == 0) {
        float c[M], A[M][M];
#pragma unroll
        for (int i = 0; i < M; i++) c[i] = sacc[i];
        int ai = M;
#pragma unroll
        for (int j = 0; j < M; j++)
#pragma unroll
            for (int k = j; k < M; k++) {
                float s = sacc[ai++];
                A[j][k] = s;
                A[k][j] = s;
            }
#pragma unroll
        for (int i = 0; i < M; i++)
#pragma unroll
            for (int j = 0; j < M; j++)
                A[i][j] = fmaf(1e-5f, K[i * M + j], A[i][j]);

        // fp32 Gaussian elimination with partial pivoting
        for (int col = 0; col < M; col++) {
            int piv = col;
            for (int r = col + 1; r < M; r++)
                if (fabsf(A[r][col]) > fabsf(A[piv][col])) piv = r;
            if (piv != col) {
                for (int cc = 0; cc < M; cc++) {
                    float t = A[col][cc]; A[col][cc] = A[piv][cc]; A[piv][cc] = t;
                }
                float tb = c[col]; c[col] = c[piv]; c[piv] = tb;
            }
            float inv = 1.0f / A[col][col];
            for (int r = col + 1; r < M; r++) {
                float f = A[r][col] * inv;
                for (int cc = col; cc < M; cc++)
                    A[r][cc] = fmaf(-f, A[col][cc], A[r][cc]);
                c[r] = fmaf(-f, c[col], c[r]);
            }
        }
        float y[M];
        for (int r = M - 1; r >= 0; r--) {
            float s = c[r];
            for (int cc = r + 1; cc < M; cc++) s = fmaf(-A[r][cc], y[cc], s);
            y[r] = s / A[r][r];
        }
#pragma unroll
        for (int i = 0; i < M; i++) g_y[i] = y[i];
    }
}

// ---------------------------------------------------------------------------
// Kernel 4: map pass, f32x2-packed:  out = dv * (g + t.y) / eps
// ---------------------------------------------------------------------------
__global__ void __launch_bounds__(NTHREADS, 4)
kwng_pass2(const float* __restrict__ T, const float* __restrict__ g,
           float* __restrict__ out, int D) {
    uint64_t qpk2[15], y2[M];
#pragma unroll
    for (int i = 0; i < 15; i++) {
        float q = g_qpk[i];
        qpk2[i] = pk2(q, q);
    }
#pragma unroll
    for (int i = 0; i < M; i++) {
        float yv = g_y[i];
        y2[i] = pk2(yv, yv);
    }
    const uint64_t eps2 = pk2(1e5f, 1e5f);   // 1/eps

    const float4* __restrict__ T4 = (const float4*)T;
    const float4* __restrict__ g4 = (const float4*)g;
    float4* __restrict__ o4 = (float4*)out;
    const int n4 = D >> 2;

    for (int i = blockIdx.x * blockDim.x + threadIdx.x; i < n4;
         i += gridDim.x * blockDim.x) {
        int idx = n4 - 1 - i;
        float4 tv[M];
#pragma unroll
        for (int j = 0; j < M; j++) tv[j] = T4[(size_t)j * n4 + idx];
        float4 gv = g4[idx];
        const uint64_t* gpp = reinterpret_cast<const uint64_t*>(&gv);
        float4 ov;
        uint64_t* opp = reinterpret_cast<uint64_t*>(&ov);
#pragma unroll
        for (int pr = 0; pr < 2; pr++) {
            uint64_t t2[M];
#pragma unroll
            for (int j = 0; j < M; j++)
                t2[j] = reinterpret_cast<const uint64_t*>(&tv[j])[pr];
            uint64_t ss2;
            {
                int qi = 0;
                uint64_t inner = mul2(qpk2[qi++], t2[0]);
#pragma unroll
                for (int k = 1; k < M; k++) inner = fma2(qpk2[qi++], t2[k], inner);
                ss2 = mul2(inner, t2[0]);
#pragma unroll
                for (int j = 1; j < M; j++) {
                    inner = mul2(qpk2[qi++], t2[j]);
#pragma unroll
                    for (int k = j + 1; k < M; k++)
                        inner = fma2(qpk2[qi++], t2[k], inner);
                    ss2 = fma2(inner, t2[j], ss2);
                }
            }
            uint64_t dv2 = dv2_from_ss2(ss2);
            uint64_t cond2 = mul2(y2[0], t2[0]);
#pragma unroll
            for (int j = 1; j < M; j++) cond2 = fma2(y2[j], t2[j], cond2);
            uint64_t s2 = add2(gpp[pr], cond2);
            s2 = mul2(s2, eps2);
            opp[pr] = mul2(dv2, s2);
        }
        __stcs(&o4[idx], ov);
    }
}

// ---------------------------------------------------------------------------
extern "C" void kernel_launch(void* const* d_in, const int* in_sizes, int n_in,
                              void* d_out, int out_size) {
    const float* K = (const float*)d_in[0];   // [5,5]
    const float* T = (const float*)d_in[1];   // [5, D]
    const float* g = (const float*)d_in[2];   // [D]
    float* out = (float*)d_out;               // [D]
    int D = in_sizes[2];

    kwng_setup<<<1, 1>>>(K);
    kwng_pass1<<<NB1, NTHREADS>>>(T, g, D);
    kwng_reduce_solve<<<1, NACC * 32>>>(K);
    kwng_pass2<<<NB2, NTHREADS>>>(T, g, out, D);
}

// round 6
// speedup vs baseline: 1.4393x; 1.0229x over previous
#include <cuda_runtime.h>
#include <math.h>
#include <stdint.h>

#define M 5
#define NACC 20              // c[5] + packed upper Gram S[15]
#define NB1 888              // pass1 grid: 148 SMs * 3 CTAs * 2 waves
#define NB2 1184             // pass2 grid
#define NTHREADS 256

__device__ float  g_qpk[15];         // Q = K^-1 packed upper, off-diag doubled
__device__ float  g_y[M];
__device__ double g_partials[NB1 * NACC];

// ---- f32x2 packed helpers (sm_103a) ---------------------------------------
__device__ __forceinline__ uint64_t pk2(float a, float b) {
    uint64_t r;
    asm("mov.b64 %0, {%1, %2};" : "=l"(r) : "f"(a), "f"(b));
    return r;
}
__device__ __forceinline__ void upk2(float& a, float& b, uint64_t v) {
    asm("mov.b64 {%0, %1}, %2;" : "=f"(a), "=f"(b) : "l"(v));
}
__device__ __forceinline__ uint64_t fma2(uint64_t a, uint64_t b, uint64_t c) {
    uint64_t d;
    asm("fma.rn.f32x2 %0, %1, %2, %3;" : "=l"(d) : "l"(a), "l"(b), "l"(c));
    return d;
}
__device__ __forceinline__ uint64_t mul2(uint64_t a, uint64_t b) {
    uint64_t d;
    asm("mul.rn.f32x2 %0, %1, %2;" : "=l"(d) : "l"(a), "l"(b));
    return d;
}
__device__ __forceinline__ uint64_t add2(uint64_t a, uint64_t b) {
    uint64_t d;
    asm("add.rn.f32x2 %0, %1, %2;" : "=l"(d) : "l"(a), "l"(b));
    return d;
}
// packed ss = t^T Q t (upper-packed Q, off-diag pre-doubled)
__device__ __forceinline__ uint64_t sstQt2(const uint64_t* qpk2, const uint64_t* t2) {
    int qi = 0;
    uint64_t inner = mul2(qpk2[qi++], t2[0]);
#pragma unroll
    for (int k = 1; k < M; k++) inner = fma2(qpk2[qi++], t2[k], inner);
    uint64_t ss2 = mul2(inner, t2[0]);
#pragma unroll
    for (int j = 1; j < M; j++) {
        inner = mul2(qpk2[qi++], t2[j]);
#pragma unroll
        for (int k = j + 1; k < M; k++) inner = fma2(qpk2[qi++], t2[k], inner);
        ss2 = fma2(inner, t2[j], ss2);
    }
    return ss2;
}
// dv = 1/(sqrt(ss)+1e-8) ≈ r - 1e-8*r^2, r = rsqrt(ss)
__device__ __forceinline__ float dv_from_ss(float ss) {
    float r = rsqrtf(fmaxf(ss, 1e-16f));
    return fmaf(-1e-8f * r, r, r);
}
__device__ __forceinline__ uint64_t dv2_from_ss2(uint64_t ss2) {
    float sa, sb;
    upk2(sa, sb, ss2);
    return pk2(dv_from_ss(sa), dv_from_ss(sb));
}

// ---------------------------------------------------------------------------
// Kernel 1: Q = K^-1 via fp32 Gauss-Jordan with partial pivoting (1 thread)
// ---------------------------------------------------------------------------
__global__ void kwng_setup(const float* __restrict__ K) {
    float A[M][M], Q[M][M];
#pragma unroll
    for (int i = 0; i < M; i++)
#pragma unroll
        for (int j = 0; j < M; j++) {
            A[i][j] = K[i * M + j];
            Q[i][j] = (i == j) ? 1.0f : 0.0f;
        }
    for (int col = 0; col < M; col++) {
        int piv = col;
        for (int r = col + 1; r < M; r++)
            if (fabsf(A[r][col]) > fabsf(A[piv][col])) piv = r;
        if (piv != col) {
            for (int c = 0; c < M; c++) {
                float t = A[col][c]; A[col][c] = A[piv][c]; A[piv][c] = t;
                t = Q[col][c]; Q[col][c] = Q[piv][c]; Q[piv][c] = t;
            }
        }
        float inv = 1.0f / A[col][col];
        for (int c = 0; c < M; c++) { A[col][c] *= inv; Q[col][c] *= inv; }
        for (int r = 0; r < M; r++) {
            if (r == col) continue;
            float f = A[r][col];
            for (int c = 0; c < M; c++) {
                A[r][c] = fmaf(-f, A[col][c], A[r][c]);
                Q[r][c] = fmaf(-f, Q[col][c], Q[r][c]);
            }
        }
    }
    int qi = 0;
#pragma unroll
    for (int j = 0; j < M; j++)
#pragma unroll
        for (int k = j; k < M; k++) {
            float q = 0.5f * (Q[j][k] + Q[k][j]);
            g_qpk[qi++] = (k == j) ? q : 2.0f * q;
        }
}

// ---------------------------------------------------------------------------
// Kernel 2: streaming reduction pass — packed ss, scalar accumulation
//   3 CTAs/SM (24 warps) with <=85 regs
// ---------------------------------------------------------------------------
__global__ void __launch_bounds__(NTHREADS, 3)
kwng_pass1(const float* __restrict__ T, const float* __restrict__ g, int D) {
    uint64_t qpk2[15];
#pragma unroll
    for (int i = 0; i < 15; i++) {
        float q = g_qpk[i];
        qpk2[i] = pk2(q, q);
    }
    float acc[NACC];
#pragma unroll
    for (int a = 0; a < NACC; a++) acc[a] = 0.0f;

    const float4* __restrict__ T4 = (const float4*)T;
    const float4* __restrict__ g4 = (const float4*)g;
    const int n4 = D >> 2;

    for (int idx = blockIdx.x * blockDim.x + threadIdx.x; idx < n4;
         idx += gridDim.x * blockDim.x) {
        float4 tv[M];
#pragma unroll
        for (int j = 0; j < M; j++) tv[j] = T4[(size_t)j * n4 + idx];
        float4 gv = g4[idx];
        const float* tp = reinterpret_cast<const float*>(tv);
        const float* gp = reinterpret_cast<const float*>(&gv);
#pragma unroll
        for (int pr = 0; pr < 2; pr++) {
            uint64_t t2[M];
#pragma unroll
            for (int j = 0; j < M; j++)
                t2[j] = reinterpret_cast<const uint64_t*>(&tv[j])[pr];
            uint64_t ss2 = sstQt2(qpk2, t2);
            float s0, s1;
            upk2(s0, s1, ss2);
#pragma unroll
            for (int h = 0; h < 2; h++) {
                int lane = pr * 2 + h;
                float dv = dv_from_ss(h ? s1 : s0);
                float t[M];
#pragma unroll
                for (int j = 0; j < M; j++) t[j] = tp[j * 4 + lane];
                float dvg = dv * gp[lane];
#pragma unroll
                for (int j = 0; j < M; j++) acc[j] = fmaf(t[j], dvg, acc[j]);
                int ai = M;
#pragma unroll
                for (int j = 0; j < M; j++) {
                    float u = dv * t[j];
#pragma unroll
                    for (int k = j; k < M; k++) {
                        acc[ai] = fmaf(u, t[k], acc[ai]);
                        ai++;
                    }
                }
            }
        }
    }

    __shared__ float sred[NTHREADS / 32][NACC];
    int lane = threadIdx.x & 31;
    int warp = threadIdx.x >> 5;
#pragma unroll
    for (int a = 0; a < NACC; a++) {
        float v = acc[a];
#pragma unroll
        for (int off = 16; off > 0; off >>= 1)
            v += __shfl_down_sync(0xffffffffu, v, off);
        if (lane == 0) sred[warp][a] = v;
    }
    __syncthreads();
    if (threadIdx.x < NACC) {
        double s = 0.0;
#pragma unroll
        for (int w = 0; w < NTHREADS / 32; w++) s += (double)sred[w][threadIdx.x];
        g_partials[(size_t)blockIdx.x * NACC + threadIdx.x] = s;
    }
}

// ---------------------------------------------------------------------------
// Kernel 3: reduce partials + fp32 tiny solve:  y = (S + eps*K)^-1 c
// ---------------------------------------------------------------------------
__global__ void kwng_reduce_solve(const float* __restrict__ K) {
    __shared__ float sacc[NACC];
    int a = threadIdx.x >> 5;
    int lane = threadIdx.x & 31;
    if (a < NACC) {
        double s = 0.0;
        for (int b = lane; b < NB1; b += 32)
            s += g_partials[(size_t)b * NACC + a];
#pragma unroll
        for (int off = 16; off > 0; off >>= 1)
            s += __shfl_down_sync(0xffffffffu, s, off);
        if (lane == 0) sacc[a] = (float)s;
    }
    __syncthreads();
    if (threadIdx.x == 0) {
        float c[M], A[M][M];
#pragma unroll
        for (int i = 0; i < M; i++) c[i] = sacc[i];
        int ai = M;
#pragma unroll
        for (int j = 0; j < M; j++)
#pragma unroll
            for (int k = j; k < M; k++) {
                float s = sacc[ai++];
                A[j][k] = s;
                A[k][j] = s;
            }
#pragma unroll
        for (int i = 0; i < M; i++)
#pragma unroll
            for (int j = 0; j < M; j++)
                A[i][j] = fmaf(1e-5f, K[i * M + j], A[i][j]);

        for (int col = 0; col < M; col++) {
            int piv = col;
            for (int r = col + 1; r < M; r++)
                if (fabsf(A[r][col]) > fabsf(A[piv][col])) piv = r;
            if (piv != col) {
                for (int cc = 0; cc < M; cc++) {
                    float t = A[col][cc]; A[col][cc] = A[piv][cc]; A[piv][cc] = t;
                }
                float tb = c[col]; c[col] = c[piv]; c[piv] = tb;
            }
            float inv = 1.0f / A[col][col];
            for (int r = col + 1; r < M; r++) {
                float f = A[r][col] * inv;
                for (int cc = col; cc < M; cc++)
                    A[r][cc] = fmaf(-f, A[col][cc], A[r][cc]);
                c[r] = fmaf(-f, c[col], c[r]);
            }
        }
        float y[M];
        for (int r = M - 1; r >= 0; r--) {
            float s = c[r];
            for (int cc = r + 1; cc < M; cc++) s = fmaf(-A[r][cc], y[cc], s);
            y[r] = s / A[r][r];
        }
#pragma unroll
        for (int i = 0; i < M; i++) g_y[i] = y[i];
    }
}

// ---------------------------------------------------------------------------
// Kernel 4: map pass, f32x2-packed:  out = dv * (g + t.y) / eps
// ---------------------------------------------------------------------------
__global__ void __launch_bounds__(NTHREADS, 4)
kwng_pass2(const float* __restrict__ T, const float* __restrict__ g,
           float* __restrict__ out, int D) {
    uint64_t qpk2[15], y2[M];
#pragma unroll
    for (int i = 0; i < 15; i++) {
        float q = g_qpk[i];
        qpk2[i] = pk2(q, q);
    }
#pragma unroll
    for (int i = 0; i < M; i++) {
        float yv = g_y[i];
        y2[i] = pk2(yv, yv);
    }
    const uint64_t eps2 = pk2(1e5f, 1e5f);   // 1/eps

    const float4* __restrict__ T4 = (const float4*)T;
    const float4* __restrict__ g4 = (const float4*)g;
    float4* __restrict__ o4 = (float4*)out;
    const int n4 = D >> 2;

    for (int idx = blockIdx.x * blockDim.x + threadIdx.x; idx < n4;
         idx += gridDim.x * blockDim.x) {
        float4 tv[M];
#pragma unroll
        for (int j = 0; j < M; j++) tv[j] = T4[(size_t)j * n4 + idx];
        float4 gv = g4[idx];
        const uint64_t* gpp = reinterpret_cast<const uint64_t*>(&gv);
        float4 ov;
        uint64_t* opp = reinterpret_cast<uint64_t*>(&ov);
#pragma unroll
        for (int pr = 0; pr < 2; pr++) {
            uint64_t t2[M];
#pragma unroll
            for (int j = 0; j < M; j++)
                t2[j] = reinterpret_cast<const uint64_t*>(&tv[j])[pr];
            uint64_t ss2 = sstQt2(qpk2, t2);
            uint64_t dv2 = dv2_from_ss2(ss2);
            uint64_t cond2 = mul2(y2[0], t2[0]);
#pragma unroll
            for (int j = 1; j < M; j++) cond2 = fma2(y2[j], t2[j], cond2);
            uint64_t s2 = add2(gpp[pr], cond2);
            s2 = mul2(s2, eps2);
            opp[pr] = mul2(dv2, s2);
        }
        __stcs(&o4[idx], ov);
    }
}

// ---------------------------------------------------------------------------
extern "C" void kernel_launch(void* const* d_in, const int* in_sizes, int n_in,
                              void* d_out, int out_size) {
    const float* K = (const float*)d_in[0];   // [5,5]
    const float* T = (const float*)d_in[1];   // [5, D]
    const float* g = (const float*)d_in[2];   // [D]
    float* out = (float*)d_out;               // [D]
    int D = in_sizes[2];

    kwng_setup<<<1, 1>>>(K);
    kwng_pass1<<<NB1, NTHREADS>>>(T, g, D);
    kwng_reduce_solve<<<1, NACC * 32>>>(K);
    kwng_pass2<<<NB2, NTHREADS>>>(T, g, out, D);
}